// round 4
// baseline (speedup 1.0000x reference)
#include <cuda_runtime.h>
#include <cstdint>

// ---------------------------------------------------------------------------
// BigramLM forward, GB300 sm_103a.
//   build_qkv: QT/KT/VT[t][v][f] tables (520 x 32 each)
//   build_qk : EQK[pair(t,s)][tok_t][tok_s][h] = exp(q.k * 32^-0.5)  (L2)
//   build_vf : VF[t][v][:] = VT[t][v] @ Wf + bf    (FF folded)
//   main     : TWO batches per thread (ILP), 128-bit smem loads feeding
//              fma.rn.f32x2, post-hoc softmax normalization, per-row
//              smem-staged coalesced streaming stores.
// ---------------------------------------------------------------------------

#define VOCAB   65
#define NEMB    32
#define TBLK    8
#define NPAIR   36
#define NTV     (TBLK*VOCAB)        // 520

typedef unsigned long long u64;

__device__ __align__(16) float g_QT[NTV * NEMB];
__device__ __align__(16) float g_KT[NTV * NEMB];
__device__ __align__(16) float g_VT[NTV * NEMB];
__device__ __align__(16) float g_VF[NTV * NEMB];
__device__ __align__(16) float g_QK[NPAIR * VOCAB * VOCAB * 4];

// ---------------- packed f32x2 helpers --------------------------------------
__device__ __forceinline__ u64 pk2(float a, float b) {
    u64 r;
    asm("mov.b64 %0, {%1, %2};" : "=l"(r)
        : "r"(__float_as_uint(a)), "r"(__float_as_uint(b)));
    return r;
}
__device__ __forceinline__ void upk2(float& a, float& b, u64 p) {
    unsigned int x, y;
    asm("mov.b64 {%0, %1}, %2;" : "=r"(x), "=r"(y) : "l"(p));
    a = __uint_as_float(x); b = __uint_as_float(y);
}
__device__ __forceinline__ u64 fma2(u64 a, u64 b, u64 c) {
    u64 d;
    asm("fma.rn.f32x2 %0, %1, %2, %3;" : "=l"(d) : "l"(a), "l"(b), "l"(c));
    return d;
}
__device__ __forceinline__ u64 mul2(u64 a, u64 b) {
    u64 d;
    asm("mul.rn.f32x2 %0, %1, %2;" : "=l"(d) : "l"(a), "l"(b));
    return d;
}

// ---------------- stage 1: per-(t,vocab) q/k/v tables ------------------------
__global__ void build_qkv(const float* __restrict__ tok_emb,
                          const float* __restrict__ pos_emb,
                          const float* __restrict__ Wq,
                          const float* __restrict__ Wk,
                          const float* __restrict__ Wv) {
    int tv = blockIdx.x;            // 0..519
    int t  = tv / VOCAB;
    int v  = tv - t * VOCAB;
    int f  = threadIdx.x;           // 0..31 -> (h,d)
    int h  = f >> 3, d = f & 7;
    float qa = 0.f, ka = 0.f, va = 0.f;
#pragma unroll
    for (int c = 0; c < NEMB; c++) {
        float x = tok_emb[v * NEMB + c] + pos_emb[t * NEMB + c];
        int wi = (h * NEMB + c) * 8 + d;     // [H, C, hs]
        qa = fmaf(x, Wq[wi], qa);
        ka = fmaf(x, Wk[wi], ka);
        va = fmaf(x, Wv[wi], va);
    }
    g_QT[tv * NEMB + f] = qa;
    g_KT[tv * NEMB + f] = ka;
    g_VT[tv * NEMB + f] = va;
}

// ---------------- stage 2a: exp(attention-logit) table -----------------------
__global__ void build_qk() {
    int P = blockIdx.y;             // pair index 0..35
    int a = blockIdx.x;             // tok_t 0..64
    int t = 0, rem = P;
    while (rem > t) { rem -= (t + 1); t++; }
    int s = rem;
    const float scale = 0.17677669529663687f;   // 32^-0.5 (n_embed!)
    for (int u = threadIdx.x; u < VOCAB * 4; u += blockDim.x) {
        int b = u >> 2, h = u & 3;
        const float* qp = &g_QT[(t * VOCAB + a) * NEMB + h * 8];
        const float* kp = &g_KT[(s * VOCAB + b) * NEMB + h * 8];
        float acc = 0.f;
#pragma unroll
        for (int d = 0; d < 8; d++) acc = fmaf(qp[d], kp[d], acc);
        g_QK[((P * VOCAB + a) * VOCAB + b) * 4 + h] = __expf(acc * scale);
    }
}

// ---------------- stage 2b: fold FF into V table ------------------------------
__global__ void build_vf(const float* __restrict__ Wf,
                         const float* __restrict__ bf) {
    int tv = blockIdx.x;            // 0..519
    int j  = threadIdx.x;           // 0..31
    const float* vr = g_VT + tv * NEMB;
    float acc = bf[j];
#pragma unroll
    for (int c = 0; c < NEMB; c++)
        acc = fmaf(vr[c], Wf[c * NEMB + j], acc);
    g_VF[tv * NEMB + j] = acc;
}

// ---------------- stage 3: main ----------------------------------------------
// smem float offsets
#define SVF  0                          // VF rows padded to 36 floats (16B ok)
#define SWL  (NTV * 36)                 // 18720 ; Wl rows padded to 68
#define SBL  (SWL + 32 * 68)            // 20896 ; bl (68, padded)
#define STG  (SBL + 68)                 // 20964 ; staging [512][66]
#define SMEM_FLOATS (STG + 512 * 66)    // 54756
#define SMEM_BYTES  (SMEM_FLOATS * 4)   // 219,024 bytes

template<int T>
__device__ __forceinline__ void do_row(const float4* __restrict__ QK4,
                                       const float* __restrict__ sm,
                                       const int* __restrict__ tokA,
                                       const int* __restrict__ tokB,
                                       float* __restrict__ stgA,
                                       float* __restrict__ stgB)
{
    const int base = T * (T + 1) / 2;
    const int rA = tokA[T] * VOCAB, rB = tokB[T] * VOCAB;
    float4 sA = make_float4(0.f, 0.f, 0.f, 0.f);
    float4 sB = make_float4(0.f, 0.f, 0.f, 0.f);
    u64 hA[16], hB[16];
#pragma unroll
    for (int g = 0; g < 16; g++) { hA[g] = 0ULL; hB[g] = 0ULL; }

#pragma unroll
    for (int s = 0; s <= T; s++) {
        float4 eA = __ldg(&QK4[(base + s) * (VOCAB * VOCAB) + rA + tokA[s]]);
        float4 eB = __ldg(&QK4[(base + s) * (VOCAB * VOCAB) + rB + tokB[s]]);
        sA.x += eA.x; sA.y += eA.y; sA.z += eA.z; sA.w += eA.w;
        sB.x += eB.x; sB.y += eB.y; sB.z += eB.z; sB.w += eB.w;
        u64 wA[4] = { pk2(eA.x, eA.x), pk2(eA.y, eA.y),
                      pk2(eA.z, eA.z), pk2(eA.w, eA.w) };
        u64 wB[4] = { pk2(eB.x, eB.x), pk2(eB.y, eB.y),
                      pk2(eB.z, eB.z), pk2(eB.w, eB.w) };
        const ulonglong2* vA =
            (const ulonglong2*)(sm + SVF + (s * VOCAB + tokA[s]) * 36);
        const ulonglong2* vB =
            (const ulonglong2*)(sm + SVF + (s * VOCAB + tokB[s]) * 36);
#pragma unroll
        for (int g = 0; g < 8; g++) {
            ulonglong2 pA = vA[g], pB = vB[g];
            hA[2 * g]     = fma2(wA[(2 * g) >> 2],     pA.x, hA[2 * g]);
            hA[2 * g + 1] = fma2(wA[(2 * g + 1) >> 2], pA.y, hA[2 * g + 1]);
            hB[2 * g]     = fma2(wB[(2 * g) >> 2],     pB.x, hB[2 * g]);
            hB[2 * g + 1] = fma2(wB[(2 * g + 1) >> 2], pB.y, hB[2 * g + 1]);
        }
    }

    // post-hoc softmax normalization + relu
    u64 iA[4], iB[4];
    {
        float a = __fdividef(1.f, sA.x), b = __fdividef(1.f, sA.y);
        float c = __fdividef(1.f, sA.z), d = __fdividef(1.f, sA.w);
        iA[0] = pk2(a, a); iA[1] = pk2(b, b); iA[2] = pk2(c, c); iA[3] = pk2(d, d);
        a = __fdividef(1.f, sB.x); b = __fdividef(1.f, sB.y);
        c = __fdividef(1.f, sB.z); d = __fdividef(1.f, sB.w);
        iB[0] = pk2(a, a); iB[1] = pk2(b, b); iB[2] = pk2(c, c); iB[3] = pk2(d, d);
    }
    float yA[32], yB[32];
#pragma unroll
    for (int g = 0; g < 16; g++) {
        float u, v;
        upk2(u, v, mul2(hA[g], iA[g >> 2]));
        yA[2 * g] = fmaxf(u, 0.f); yA[2 * g + 1] = fmaxf(v, 0.f);
        upk2(u, v, mul2(hB[g], iB[g >> 2]));
        yB[2 * g] = fmaxf(u, 0.f); yB[2 * g + 1] = fmaxf(v, 0.f);
    }

    // ---- logits, two halves of 32 outputs (+ v=64) ----
#pragma unroll
    for (int h2 = 0; h2 < 2; h2++) {
        u64 zA[16], zB[16];
        const u64* bl2 = (const u64*)(sm + SBL) + h2 * 16;
#pragma unroll
        for (int v = 0; v < 16; v++) { zA[v] = bl2[v]; zB[v] = bl2[v]; }
        float z64A = sm[SBL + 64], z64B = z64A;
#pragma unroll
        for (int j = 0; j < 32; j++) {
            u64 pA = pk2(yA[j], yA[j]);
            u64 pB = pk2(yB[j], yB[j]);
            const ulonglong2* w2 =
                (const ulonglong2*)(sm + SWL + j * 68 + h2 * 32);
#pragma unroll
            for (int g = 0; g < 8; g++) {
                ulonglong2 w = w2[g];
                zA[2 * g]     = fma2(pA, w.x, zA[2 * g]);
                zA[2 * g + 1] = fma2(pA, w.y, zA[2 * g + 1]);
                zB[2 * g]     = fma2(pB, w.x, zB[2 * g]);
                zB[2 * g + 1] = fma2(pB, w.y, zB[2 * g + 1]);
            }
            if (h2 == 1) {
                float wl = sm[SWL + j * 68 + 64];
                z64A = fmaf(yA[j], wl, z64A);
                z64B = fmaf(yB[j], wl, z64B);
            }
        }
        if ((T & 1) == 0) {
            // even row: staging S[k] = z[k]; u64 stores aligned
            u64* dA = (u64*)stgA; u64* dB = (u64*)stgB;
#pragma unroll
            for (int v = 0; v < 16; v++) {
                dA[h2 * 16 + v] = zA[v];
                dB[h2 * 16 + v] = zB[v];
            }
            if (h2 == 1) { stgA[64] = z64A; stgB[64] = z64B; }
        } else {
            // odd row: S[0]=z[0], S[m+1]=z[m] (m>=1) so flush u64s stay aligned
#pragma unroll
            for (int v = 0; v < 16; v++) {
                float u, w;
                int k = h2 * 32 + 2 * v;
                upk2(u, w, zA[v]);
                stgA[k == 0 ? 0 : k + 1] = u; stgA[k + 2] = w;
                upk2(u, w, zB[v]);
                stgB[k == 0 ? 0 : k + 1] = u; stgB[k + 2] = w;
            }
            if (h2 == 1) { stgA[65] = z64A; stgB[65] = z64B; }
        }
    }
}

__global__ __launch_bounds__(256, 1)
void bigram_main(const int* __restrict__ idx,
                 const float* __restrict__ Wl, const float* __restrict__ bl,
                 float* __restrict__ out, int nb) {
    extern __shared__ float sm[];
    int tid = threadIdx.x;

    // --- cooperative smem fill (VF row = 32 floats = 8 ulonglong2!) ---
    for (int r = tid; r < NTV; r += 256) {
        const ulonglong2* src = (const ulonglong2*)(g_VF + r * NEMB);
        ulonglong2* dst = (ulonglong2*)(sm + SVF + r * 36);
#pragma unroll
        for (int g = 0; g < 8; g++) dst[g] = src[g];
    }
    for (int i = tid; i < 32 * 68; i += 256) {
        int j = i / 68, v = i - j * 68;
        sm[SWL + i] = (v < 65) ? Wl[j * 65 + v] : 0.f;
    }
    if (tid < 68) sm[SBL + tid] = (tid < 65) ? bl[tid] : 0.f;
    __syncthreads();

    const float4* QK4 = (const float4*)g_QK;
    int ntile = (nb + 511) >> 9;

    for (int tile = blockIdx.x; tile < ntile; tile += gridDim.x) {
        int gbase = tile << 9;
        int bA = gbase + tid, bB = bA + 256;
        int bAc = min(bA, nb - 1), bBc = min(bB, nb - 1);
        int tokA[8], tokB[8];
        {
            const int4* pa = (const int4*)(idx + (size_t)bAc * 8);
            int4 x0 = __ldg(pa), x1 = __ldg(pa + 1);
            tokA[0] = x0.x; tokA[1] = x0.y; tokA[2] = x0.z; tokA[3] = x0.w;
            tokA[4] = x1.x; tokA[5] = x1.y; tokA[6] = x1.z; tokA[7] = x1.w;
            const int4* pb = (const int4*)(idx + (size_t)bBc * 8);
            int4 y0 = __ldg(pb), y1 = __ldg(pb + 1);
            tokB[0] = y0.x; tokB[1] = y0.y; tokB[2] = y0.z; tokB[3] = y0.w;
            tokB[4] = y1.x; tokB[5] = y1.y; tokB[6] = y1.z; tokB[7] = y1.w;
        }
        float* stgA = sm + STG + tid * 66;
        float* stgB = sm + STG + (tid + 256) * 66;

#define ROW(T)                                                              \
        do_row<T>(QK4, sm, tokA, tokB, stgA, stgB);                         \
        __syncthreads();                                                    \
        {                                                                   \
            const int srcoff = ((T) & 1) ? 2 : 0;                           \
            const int dstoff = ((T) & 1) ? 1 : 0;                           \
            for (int i = tid; i < 512 * 32; i += 256) {                     \
                int row = i >> 5, g = i & 31;                               \
                int b = gbase + row;                                        \
                if (b < nb) {                                               \
                    u64 val = *(const u64*)(sm + STG + row * 66             \
                                            + srcoff + 2 * g);              \
                    __stcs((u64*)(out + (size_t)b * 520 + (T) * 65          \
                                  + dstoff) + g, val);                      \
                }                                                           \
            }                                                               \
            for (int i = tid; i < 512; i += 256) {                          \
                int b = gbase + i;                                          \
                if (b < nb) {                                               \
                    int so = ((T) & 1) ? 0 : 64;                            \
                    int go = ((T) & 1) ? 0 : 64;                            \
                    __stcs(out + (size_t)b * 520 + (T) * 65 + go,           \
                           sm[STG + i * 66 + so]);                          \
                }                                                           \
            }                                                               \
        }                                                                   \
        __syncthreads();

        ROW(0) ROW(1) ROW(2) ROW(3) ROW(4) ROW(5) ROW(6) ROW(7)
#undef ROW
    }
}

// ---------------------------------------------------------------------------
extern "C" void kernel_launch(void* const* d_in, const int* in_sizes, int n_in,
                              void* d_out, int out_size) {
    const int*   idx     = (const int*)  d_in[0];
    const float* tok_emb = (const float*)d_in[1];
    const float* pos_emb = (const float*)d_in[2];
    const float* Wq      = (const float*)d_in[3];
    const float* Wk      = (const float*)d_in[4];
    const float* Wv      = (const float*)d_in[5];
    const float* Wf      = (const float*)d_in[6];
    const float* bf      = (const float*)d_in[7];
    const float* Wl      = (const float*)d_in[8];
    const float* bl      = (const float*)d_in[9];
    float* out = (float*)d_out;

    int nb = in_sizes[0] / TBLK;   // 131072

    cudaFuncSetAttribute(bigram_main,
                         cudaFuncAttributeMaxDynamicSharedMemorySize, SMEM_BYTES);

    int dev = 0, nsm = 148;
    cudaGetDevice(&dev);
    cudaDeviceGetAttribute(&nsm, cudaDevAttrMultiProcessorCount, dev);

    build_qkv<<<NTV, 32>>>(tok_emb, pos_emb, Wq, Wk, Wv);
    build_qk<<<dim3(VOCAB, NPAIR), 256>>>();
    build_vf<<<NTV, 32>>>(Wf, bf);

    bigram_main<<<nsm, 256, SMEM_BYTES>>>(idx, Wl, bl, out, nb);
}